// round 1
// baseline (speedup 1.0000x reference)
#include <cuda_runtime.h>

#define D_FEAT 64

// Lower bound in sorted int array: first index i with a[i] >= key.
__device__ __forceinline__ int lower_bound_i32(const int* __restrict__ a, int n, int key) {
    int lo = 0, hi = n;
    while (lo < hi) {
        int mid = (lo + hi) >> 1;
        if (__ldg(a + mid) < key) lo = mid + 1;
        else hi = mid;
    }
    return lo;
}

// One warp per output node. target_index is sorted, so node v's edges are the
// contiguous range [lower_bound(v), lower_bound(v+1)). Lane l accumulates
// features {2l, 2l+1} as a float2. No atomics, fully coalesced gathers/stores.
__global__ __launch_bounds__(256) void mp_warp_per_node_kernel(
    const float*  __restrict__ x,      // [n_nodes, 64]
    const float*  __restrict__ ev,     // [n_edges]
    const int*    __restrict__ tgt,    // [n_edges], sorted
    const int*    __restrict__ src,    // [n_edges]
    float*        __restrict__ out,    // [n_nodes, 64]
    int n_nodes, int n_edges)
{
    const int warp = (blockIdx.x * blockDim.x + threadIdx.x) >> 5;
    const int lane = threadIdx.x & 31;
    if (warp >= n_nodes) return;
    const int node = warp;

    // Lanes 0 and 1 search for node and node+1 concurrently; broadcast.
    int res = 0;
    if (lane < 2) res = lower_bound_i32(tgt, n_edges, node + lane);
    const int start = __shfl_sync(0xffffffffu, res, 0);
    const int end   = __shfl_sync(0xffffffffu, res, 1);

    const float2* __restrict__ xf2 = (const float2*)x;

    float ax = 0.0f, ay = 0.0f;
    int e = start;
    // 2x unroll for memory-level parallelism on the L2-resident gathers.
    for (; e + 1 < end; e += 2) {
        const int   s0 = __ldg(src + e);
        const int   s1 = __ldg(src + e + 1);
        const float w0 = __ldg(ev + e);
        const float w1 = __ldg(ev + e + 1);
        const float2 v0 = __ldg(&xf2[(size_t)s0 * 32 + lane]);
        const float2 v1 = __ldg(&xf2[(size_t)s1 * 32 + lane]);
        ax = fmaf(w0, v0.x, ax);
        ay = fmaf(w0, v0.y, ay);
        ax = fmaf(w1, v1.x, ax);
        ay = fmaf(w1, v1.y, ay);
    }
    if (e < end) {
        const int   s0 = __ldg(src + e);
        const float w0 = __ldg(ev + e);
        const float2 v0 = __ldg(&xf2[(size_t)s0 * 32 + lane]);
        ax = fmaf(w0, v0.x, ax);
        ay = fmaf(w0, v0.y, ay);
    }

    // Every node writes its full row (zeros for isolated nodes),
    // so the 0xAA-poisoned output needs no separate memset.
    float2* __restrict__ of2 = (float2*)out;
    of2[(size_t)node * 32 + lane] = make_float2(ax, ay);
}

extern "C" void kernel_launch(void* const* d_in, const int* in_sizes, int n_in,
                              void* d_out, int out_size) {
    const float* x   = (const float*)d_in[0];
    const float* ev  = (const float*)d_in[1];
    const int*   tgt = (const int*)d_in[2];
    const int*   src = (const int*)d_in[3];
    float* out = (float*)d_out;

    const int n_edges = in_sizes[1];
    const int n_nodes = out_size / D_FEAT;

    const int threads = 256;                 // 8 warps/block
    const int warps_needed = n_nodes;
    const int blocks = (warps_needed * 32 + threads - 1) / threads;
    mp_warp_per_node_kernel<<<blocks, threads>>>(x, ev, tgt, src, out, n_nodes, n_edges);
}

// round 2
// speedup vs baseline: 1.4406x; 1.4406x over previous
#include <cuda_runtime.h>

#define D_FEAT 64
#define MAX_NODES 100000

// Scratch: CSR-style row pointer, rebuilt deterministically every launch.
__device__ int g_row_ptr[MAX_NODES + 1];

// Build row_ptr from the sorted target index: row_ptr[v] = first edge e with
// tgt[e] >= v. Boundary ranges (tgt[e-1], tgt[e]] are disjoint across e, so
// all writes are race-free and the result is deterministic.
__global__ void build_row_ptr_kernel(const int* __restrict__ tgt,
                                     int n_edges, int n_nodes) {
    const int e = blockIdx.x * blockDim.x + threadIdx.x;
    if (e >= n_edges) return;
    const int cur  = __ldg(tgt + e);
    const int prev = (e == 0) ? -1 : __ldg(tgt + e - 1);
    for (int v = prev + 1; v <= cur; ++v) g_row_ptr[v] = e;
    if (e == n_edges - 1) {
        for (int v = cur + 1; v <= n_nodes; ++v) g_row_ptr[v] = n_edges;
    }
}

// One warp per output node. Half-warp h (lanes 16h..16h+15) processes edges
// with parity h; lane's quarter-row is a float4 (features 4*hl .. 4*hl+3).
// Edge metadata (src, ev) is loaded cooperatively once per 32-edge batch and
// broadcast via shfl. No atomics; fully coalesced 256B gathers and stores.
__global__ __launch_bounds__(256) void mp_gather_kernel(
    const float* __restrict__ x,    // [n_nodes, 64]
    const float* __restrict__ ev,   // [n_edges]
    const int*   __restrict__ src,  // [n_edges]
    float*       __restrict__ out,  // [n_nodes, 64]
    int n_nodes)
{
    const int warp = (blockIdx.x * blockDim.x + threadIdx.x) >> 5;
    if (warp >= n_nodes) return;
    const int lane = threadIdx.x & 31;
    const int half = lane >> 4;   // 0 or 1: which edge-parity this lane serves
    const int hl   = lane & 15;   // position within half-warp
    const int node = warp;

    const int start = __ldg(&g_row_ptr[node]);
    const int end   = __ldg(&g_row_ptr[node + 1]);

    const float4* __restrict__ xf4 = (const float4*)x;
    float4 acc = make_float4(0.f, 0.f, 0.f, 0.f);

    for (int base = start; base < end; base += 32) {
        const int cnt = min(32, end - base);
        // Cooperative metadata load: lane l owns edge base+l of this batch.
        int   s_l = 0;
        float w_l = 0.f;
        if (lane < cnt) {
            s_l = __ldg(src + base + lane);
            w_l = __ldg(ev  + base + lane);
        }
        const int iters = (cnt + 1) >> 1;  // both halves run the same count
        #pragma unroll 2
        for (int k = 0; k < iters; ++k) {
            const int j  = 2 * k + half;
            const int jj = min(j, cnt - 1);          // keep shfl convergent
            const int   s = __shfl_sync(0xffffffffu, s_l, jj);
            float       w = __shfl_sync(0xffffffffu, w_l, jj);
            if (j >= cnt) w = 0.f;                   // padded edge adds zero
            const float4 v = __ldg(&xf4[(size_t)s * 16 + hl]);
            acc.x = fmaf(w, v.x, acc.x);
            acc.y = fmaf(w, v.y, acc.y);
            acc.z = fmaf(w, v.z, acc.z);
            acc.w = fmaf(w, v.w, acc.w);
        }
    }

    // Combine the two half-warp partial sums.
    acc.x += __shfl_xor_sync(0xffffffffu, acc.x, 16);
    acc.y += __shfl_xor_sync(0xffffffffu, acc.y, 16);
    acc.z += __shfl_xor_sync(0xffffffffu, acc.z, 16);
    acc.w += __shfl_xor_sync(0xffffffffu, acc.w, 16);

    if (half == 0) {
        float4* __restrict__ of4 = (float4*)out;
        of4[(size_t)node * 16 + hl] = acc;  // 16 lanes x 16B = 256B coalesced
    }
}

extern "C" void kernel_launch(void* const* d_in, const int* in_sizes, int n_in,
                              void* d_out, int out_size) {
    const float* x   = (const float*)d_in[0];
    const float* ev  = (const float*)d_in[1];
    const int*   tgt = (const int*)d_in[2];
    const int*   src = (const int*)d_in[3];
    float* out = (float*)d_out;

    const int n_edges = in_sizes[1];
    const int n_nodes = out_size / D_FEAT;

    {
        const int threads = 256;
        const int blocks  = (n_edges + threads - 1) / threads;
        build_row_ptr_kernel<<<blocks, threads>>>(tgt, n_edges, n_nodes);
    }
    {
        const int threads = 256;  // 8 warps/block, 1 node/warp
        const int blocks  = (n_nodes * 32 + threads - 1) / threads;
        mp_gather_kernel<<<blocks, threads>>>(x, ev, src, out, n_nodes);
    }
}